// round 1
// baseline (speedup 1.0000x reference)
#include <cuda_runtime.h>
#include <cuda_bf16.h>
#include <math.h>

// ---------------------------------------------------------------------------
// WithinSubjectTripletLoss: B=8192, D=128 fp32 embeddings, 16 subjects, 6 labels.
// Strategy: only within-subject pairs matter -> bucket by subject, compute
// per-subject 64x64 distance tiles with a register-tiled fp32 GEMM and an
// argmax/argmin epilogue (hardest positive / hardest negative), then the
// triplet terms and a deterministic reduction.
// ---------------------------------------------------------------------------

#define MAXB   8192
#define NS     16
#define D      128
#define PITCH  68          // K-major smem pitch (floats): conflict-free f4 reads
#define TM     64
#define TN     64
#define SMEM_BYTES (2 * D * PITCH * 4)
#define EPSV   1e-6f
#define MARGIN 0.8f
#define NEGINF (-3.0e38f)
#define POSINF ( 3.0e38f)

__device__ float g_sq[MAXB];
__device__ int   g_cnt[NS];
__device__ int   g_off[NS];
__device__ int   g_cur[NS];
__device__ int   g_list[MAXB];
__device__ int   g_pIdx[MAXB];
__device__ int   g_nIdx[MAXB];
__device__ float g_per[MAXB];

// ------------------------------- init --------------------------------------
__global__ void k_init() {
    int t = threadIdx.x;
    if (t < NS) g_cnt[t] = 0;
}

// ---------------------- sq norms + subject counts --------------------------
__global__ void k_sq_count(const float* __restrict__ emb,
                           const int* __restrict__ sbj, int B) {
    int warp = (blockIdx.x * blockDim.x + threadIdx.x) >> 5;
    int l = threadIdx.x & 31;
    if (warp >= B) return;
    const float* e = emb + (size_t)warp * D;
    float s = 0.f;
#pragma unroll
    for (int c = 0; c < 4; c++) { float v = e[l + 32 * c]; s += v * v; }
#pragma unroll
    for (int d = 16; d; d >>= 1) s += __shfl_xor_sync(0xFFFFFFFFu, s, d);
    if (l == 0) {
        g_sq[warp] = s;
        int sb = sbj[warp];
        if ((unsigned)sb < (unsigned)NS) atomicAdd(&g_cnt[sb], 1);
    }
}

// ------------------------------ prefix -------------------------------------
__global__ void k_prefix() {
    if (threadIdx.x == 0) {
        int run = 0;
        for (int s = 0; s < NS; s++) {
            g_off[s] = run;
            g_cur[s] = run;
            run += g_cnt[s];
        }
    }
}

// ------------------------------ scatter ------------------------------------
__global__ void k_scatter(const int* __restrict__ sbj, int B) {
    int i = blockIdx.x * blockDim.x + threadIdx.x;
    if (i >= B) return;
    int s = sbj[i];
    if ((unsigned)s < (unsigned)NS) {
        int pos = atomicAdd(&g_cur[s], 1);
        g_list[pos] = i;
    }
}

// ----------------------- tile loader (gmem -> K-major smem) ----------------
__device__ __forceinline__ void load_tile(const float* __restrict__ emb,
                                          const int* __restrict__ labels,
                                          int listPos, int nv,
                                          float* sT, int* tIdx, int* tLab,
                                          float* tSq) {
    int t = threadIdx.x;           // 256 threads
    int w = t >> 5, l = t & 31;
#pragma unroll
    for (int rr = w; rr < TM; rr += 8) {
        int gi = -1;
        if (rr < nv) gi = g_list[listPos + rr];
        const float* src = emb + (size_t)(gi >= 0 ? gi : 0) * D;
#pragma unroll
        for (int c = 0; c < 4; c++) {
            float v = (gi >= 0) ? src[l + 32 * c] : 0.0f;
            sT[(l + 32 * c) * PITCH + rr] = v;
        }
        if (l == 0) {
            tIdx[rr] = gi;
            tLab[rr] = (gi >= 0) ? labels[gi] : -1;
            tSq[rr]  = (gi >= 0) ? g_sq[gi] : 0.0f;
        }
    }
}

// ------------- main: per-subject tiled d2 + hardest pos/neg ----------------
__global__ void __launch_bounds__(256, 1)
k_compute(const float* __restrict__ emb, const int* __restrict__ labels) {
    extern __shared__ float sm[];
    float* sA = sm;                // [D][PITCH] K-major anchor tile
    float* sB = sm + D * PITCH;    // [D][PITCH] K-major candidate tile
    __shared__ int   aIdx[TM], bIdx[TN], aLab[TM], bLab[TN];
    __shared__ float aSq[TM], bSq[TN];

    int s = blockIdx.y;
    int cnt = g_cnt[s];
    int aBase = blockIdx.x * TM;
    if (aBase >= cnt) return;
    int off = g_off[s];
    int nA = min(TM, cnt - aBase);

    load_tile(emb, labels, off + aBase, nA, sA, aIdx, aLab, aSq);

    int tid = threadIdx.x;
    int tx = tid & 15, ty = tid >> 4;

    float pV[4], nV[4];
    int   pI[4], nI[4];
#pragma unroll
    for (int i = 0; i < 4; i++) { pV[i] = NEGINF; pI[i] = -1; nV[i] = POSINF; nI[i] = -1; }

    for (int bBase = 0; bBase < cnt; bBase += TN) {
        __syncthreads();  // previous iter done reading sB/meta (also covers sA load)
        load_tile(emb, labels, off + bBase, min(TN, cnt - bBase), sB, bIdx, bLab, bSq);
        __syncthreads();

        float acc[4][4] = {};
#pragma unroll 4
        for (int k = 0; k < D; k++) {
            float4 a = *(const float4*)&sA[k * PITCH + ty * 4];
            float4 b = *(const float4*)&sB[k * PITCH + tx * 4];
            acc[0][0] += a.x * b.x; acc[0][1] += a.x * b.y; acc[0][2] += a.x * b.z; acc[0][3] += a.x * b.w;
            acc[1][0] += a.y * b.x; acc[1][1] += a.y * b.y; acc[1][2] += a.y * b.z; acc[1][3] += a.y * b.w;
            acc[2][0] += a.z * b.x; acc[2][1] += a.z * b.y; acc[2][2] += a.z * b.z; acc[2][3] += a.z * b.w;
            acc[3][0] += a.w * b.x; acc[3][1] += a.w * b.y; acc[3][2] += a.w * b.z; acc[3][3] += a.w * b.w;
        }

        // epilogue: update per-anchor hardest positive / hardest negative
        int al[4], ai[4]; float as_[4];
#pragma unroll
        for (int i = 0; i < 4; i++) {
            ai[i] = aIdx[ty * 4 + i]; al[i] = aLab[ty * 4 + i]; as_[i] = aSq[ty * 4 + i];
        }
#pragma unroll
        for (int j = 0; j < 4; j++) {
            int bj = bIdx[tx * 4 + j];
            if (bj < 0) continue;
            int   bl  = bLab[tx * 4 + j];
            float bsq = bSq[tx * 4 + j];
#pragma unroll
            for (int i = 0; i < 4; i++) {
                if (ai[i] < 0) continue;
                float d2 = as_[i] + bsq - 2.0f * acc[i][j];
                if (bl == al[i]) {
                    if (bj != ai[i]) {
                        if (d2 > pV[i] || (d2 == pV[i] && bj < pI[i])) { pV[i] = d2; pI[i] = bj; }
                    }
                } else {
                    if (d2 < nV[i] || (d2 == nV[i] && bj < nI[i])) { nV[i] = d2; nI[i] = bj; }
                }
            }
        }
    }

    // reduce across the 16 tx threads (half-warp, lanes differ only in bits 0..3)
    unsigned fm = 0xFFFFFFFFu;
#pragma unroll
    for (int i = 0; i < 4; i++) {
        float v = pV[i]; int ix = pI[i];
#pragma unroll
        for (int d = 8; d; d >>= 1) {
            float ov = __shfl_xor_sync(fm, v, d);
            int   oi = __shfl_xor_sync(fm, ix, d);
            if (oi >= 0 && (ix < 0 || ov > v || (ov == v && oi < ix))) { v = ov; ix = oi; }
        }
        float w = nV[i]; int jx = nI[i];
#pragma unroll
        for (int d = 8; d; d >>= 1) {
            float ow = __shfl_xor_sync(fm, w, d);
            int   oj = __shfl_xor_sync(fm, jx, d);
            if (oj >= 0 && (jx < 0 || ow < w || (ow == w && oj < jx))) { w = ow; jx = oj; }
        }
        if (tx == 0) {
            int a = aIdx[ty * 4 + i];
            if (a >= 0) { g_pIdx[a] = ix; g_nIdx[a] = jx; }
        }
    }
}

// --------------------- per-anchor triplet term -----------------------------
__global__ void k_triplet(const float* __restrict__ emb, int B) {
    int warp = (blockIdx.x * blockDim.x + threadIdx.x) >> 5;
    int l = threadIdx.x & 31;
    if (warp >= B) return;
    int p = g_pIdx[warp], n = g_nIdx[warp];
    float per = 0.0f;
    if (p >= 0 && n >= 0) {
        const float4* a  = (const float4*)(emb + (size_t)warp * D);
        const float4* pp = (const float4*)(emb + (size_t)p * D);
        const float4* nn = (const float4*)(emb + (size_t)n * D);
        float4 av = a[l], pv = pp[l], nv = nn[l];
        float sp = 0.f, sn = 0.f, d;
        d = av.x - pv.x + EPSV; sp += d * d;
        d = av.y - pv.y + EPSV; sp += d * d;
        d = av.z - pv.z + EPSV; sp += d * d;
        d = av.w - pv.w + EPSV; sp += d * d;
        d = av.x - nv.x + EPSV; sn += d * d;
        d = av.y - nv.y + EPSV; sn += d * d;
        d = av.z - nv.z + EPSV; sn += d * d;
        d = av.w - nv.w + EPSV; sn += d * d;
#pragma unroll
        for (int dd = 16; dd; dd >>= 1) {
            sp += __shfl_xor_sync(0xFFFFFFFFu, sp, dd);
            sn += __shfl_xor_sync(0xFFFFFFFFu, sn, dd);
        }
        per = fmaxf(sqrtf(sp) - sqrtf(sn) + MARGIN, 0.0f);
    }
    if (l == 0) g_per[warp] = per;
}

// ---------------- deterministic final reduction ----------------------------
__global__ void k_reduce(float* __restrict__ out, int B) {
    __shared__ float ssum[256];
    __shared__ int   scnt[256];
    int t = threadIdx.x;
    float s = 0.f; int c = 0;
    for (int i = t; i < B; i += 256) {
        s += g_per[i];
        c += (g_pIdx[i] >= 0 && g_nIdx[i] >= 0) ? 1 : 0;
    }
    ssum[t] = s; scnt[t] = c;
    __syncthreads();
#pragma unroll
    for (int d = 128; d; d >>= 1) {
        if (t < d) { ssum[t] += ssum[t + d]; scnt[t] += scnt[t + d]; }
        __syncthreads();
    }
    if (t == 0) out[0] = (scnt[0] > 0) ? (ssum[0] / (float)scnt[0]) : 0.0f;
}

// ---------------------------------------------------------------------------
extern "C" void kernel_launch(void* const* d_in, const int* in_sizes, int n_in,
                              void* d_out, int out_size) {
    const float* emb    = (const float*)d_in[0];
    const int*   labels = (const int*)d_in[1];
    const int*   sbj    = (const int*)d_in[2];
    float*       out    = (float*)d_out;
    int B = in_sizes[1];
    if (B > MAXB) B = MAXB;

    cudaFuncSetAttribute(k_compute, cudaFuncAttributeMaxDynamicSharedMemorySize,
                         SMEM_BYTES);

    k_init<<<1, 32>>>();
    k_sq_count<<<(B * 32 + 255) / 256, 256>>>(emb, sbj, B);
    k_prefix<<<1, 32>>>();
    k_scatter<<<(B + 255) / 256, 256>>>(sbj, B);
    // capacity: 32 anchor tiles * 64 = 2048 anchors per subject (B/16 ~= 512)
    k_compute<<<dim3(32, NS), 256, SMEM_BYTES>>>(emb, labels);
    k_triplet<<<(B * 32 + 255) / 256, 256>>>(emb, B);
    k_reduce<<<1, 256>>>(out, B);
}

// round 10
// speedup vs baseline: 1.4496x; 1.4496x over previous
#include <cuda_runtime.h>
#include <cuda_bf16.h>
#include <math.h>

// ---------------------------------------------------------------------------
// WithinSubjectTripletLoss (B=8192, D=128 fp32, 16 subjects, 6 labels)
// Two launches:
//   k_prep    : sq-norms (blocks 0..255) || deterministic bucket sort (block 256)
//   k_compute : per-subject tiled d2 GEMM + hardest pos/neg + fused triplet
//               epilogue + per-block partials + last-block final reduction.
// ---------------------------------------------------------------------------

#define MAXB   8192
#define NS     16
#define D      128
#define PITCH  68                        // words per feature row (64 data + 4 pad)
#define TM     64
#define TN     64
#define TILE_WORDS (D * PITCH)           // 8704 words
#define SMEM_BYTES (3 * TILE_WORDS * 4)  // sA + double-buffered sB = 104448 B
#define EPSV   1e-6f
#define MARGIN 0.8f
#define NEGINF (-3.0e38f)
#define POSINF ( 3.0e38f)
#define GX     16
#define NBLK   (GX * NS)                 // 256 compute blocks

__device__ float    g_sq[MAXB];
__device__ int      g_cnt[NS];
__device__ int      g_off[NS];
__device__ int      g_list[MAXB];
__device__ float    g_psum[NBLK];
__device__ int      g_pcnt[NBLK];
__device__ unsigned g_ctr;

// ===========================================================================
// k_prep: 257 blocks x 1024 threads.
//   blocks 0..255 : warp-per-row squared norms (32 rows per block)
//   block 256     : deterministic bucket sort by subject + counter reset
// ===========================================================================
__global__ void k_prep(const float* __restrict__ emb,
                       const int* __restrict__ sbj, int B) {
    int bid = blockIdx.x;
    int tid = threadIdx.x, w = tid >> 5, l = tid & 31;

    if (bid < 256) {                               // ---- sq norms ----
        int row = bid * 32 + w;
        if (row < B) {
            const float* e = emb + (size_t)row * D;
            float s = 0.f;
#pragma unroll
            for (int c = 0; c < 4; c++) { float v = e[l + 32 * c]; s += v * v; }
#pragma unroll
            for (int d = 16; d; d >>= 1) s += __shfl_xor_sync(0xFFFFFFFFu, s, d);
            if (l == 0) g_sq[row] = s;
        }
        return;
    }

    // ---- deterministic bucket sort ----
    __shared__ int wOff[32][NS];
    __shared__ int base[NS];
    __shared__ int cnt[NS];
    if (tid < NS) cnt[tid] = 0;
    __syncthreads();

    // pass 1: counts (warp-aggregated; integer, order-independent)
    for (int i = tid; i < B; i += 1024) {
        int s = sbj[i];
        unsigned m = __match_any_sync(__activemask(), s);
        if (l == (__ffs(m) - 1)) atomicAdd(&cnt[s], __popc(m));
    }
    __syncthreads();
    if (tid == 0) {
        int run = 0;
        for (int s = 0; s < NS; s++) {
            g_cnt[s] = cnt[s]; g_off[s] = run; base[s] = run; run += cnt[s];
        }
        g_ctr = 0;                                  // reset for this replay
    }
    __syncthreads();

    // pass 2: stable scatter (chunk asc -> warp asc -> lane asc)
    for (int chunk = 0; chunk < B; chunk += 1024) {
        int i = chunk + tid;
        int s = (i < B) ? sbj[i] : -1;
        if (l < NS) wOff[w][l] = 0;
        __syncwarp();
        int rank = 0;
        if (s >= 0) {
            unsigned m = __match_any_sync(__activemask(), s);
            rank = __popc(m & ((1u << l) - 1u));
            if (l == (__ffs(m) - 1)) wOff[w][s] = __popc(m);
        }
        __syncthreads();
        if (tid < NS) {
            int run = base[tid];
            for (int ww = 0; ww < 32; ww++) {
                int c = wOff[ww][tid]; wOff[ww][tid] = run; run += c;
            }
            base[tid] = run;
        }
        __syncthreads();
        if (s >= 0) g_list[wOff[w][s] + rank] = i;
        __syncthreads();
    }
}

// ===========================================================================
// k_compute: grid (GX, NS), 256 threads.
// smem tile layout (K-major, XOR-swizzled in 16B row groups):
//   element (row rr, feat k) -> word  k*PITCH + (((rr>>2) ^ ((k>>2)&15))<<2) + (rr&3)
// compute LDS.128 loads are conflict-free / broadcast; staging STS ~4-way.
// ===========================================================================
__global__ void __launch_bounds__(256, 1)
k_compute(const float* __restrict__ emb, const int* __restrict__ labels,
          float* __restrict__ out) {
    extern __shared__ float sm[];
    float* sA = sm;                          // anchor tile
    float* sB = sm + TILE_WORDS;             // 2 candidate buffers
    __shared__ int   aIdx[TM], aLab[TM];
    __shared__ int   bIdx[2][TN], bLab[2][TN];
    __shared__ float bSq[2][TN];
    __shared__ int   sPI[TM], sNI[TM];
    __shared__ float wSum[8];
    __shared__ int   wCnt[8];
    __shared__ bool  lastBlk;

    int tid = threadIdx.x, w = tid >> 5, l = tid & 31;
    int tx = tid & 15, ty = tid >> 4;
    int s = blockIdx.y;
    int cnt = g_cnt[s], off = g_off[s];

    float runSum = 0.f; int runCnt = 0;      // meaningful in lane 0 of each warp

    for (int aT = blockIdx.x; aT * TM < cnt; aT += GX) {
        __syncthreads();                     // WAR: prev iter done with sA/aIdx/sB
        int aBase = aT * TM;
        int nA = min(TM, cnt - aBase);

        // ---------- anchor tile: gmem -> regs -> swizzled smem ----------
        {
            float4 v[8];
#pragma unroll
            for (int r = 0; r < 8; r++) {
                int rr = w * 8 + r;
                int gi = (rr < nA) ? g_list[off + aBase + rr] : -1;
                v[r] = (gi >= 0) ? *(const float4*)(emb + (size_t)gi * D + l * 4)
                                 : make_float4(0.f, 0.f, 0.f, 0.f);
                if (l == 0) { aIdx[rr] = gi; aLab[rr] = (gi >= 0) ? labels[gi] : -1; }
            }
#pragma unroll
            for (int r = 0; r < 8; r++) {
                int rr = w * 8 + r;
                int swz = (((rr >> 2) ^ (l & 15)) << 2) + (rr & 3);
#pragma unroll
                for (int c = 0; c < 4; c++)
                    sA[(4 * l + c) * PITCH + swz] = ((const float*)&v[r])[c];
            }
        }
        __syncthreads();

        int ai[4], al[4];
#pragma unroll
        for (int i = 0; i < 4; i++) { ai[i] = aIdx[ty * 4 + i]; al[i] = aLab[ty * 4 + i]; }

        float pV[4], nV[4]; int pI[4], nI[4];
#pragma unroll
        for (int i = 0; i < 4; i++) { pV[i] = NEGINF; pI[i] = -1; nV[i] = POSINF; nI[i] = -1; }

        int nT = (cnt + TN - 1) / TN;
        float4 stg[8]; int sgi = -1, slab = -1; float ssq = 0.f;

        auto stage = [&](int t) {            // tile t: gmem -> registers
            int bBase = t * TN;
            int nB = cnt - bBase;
#pragma unroll
            for (int r = 0; r < 8; r++) {
                int rr = w * 8 + r;
                int gi = (rr < nB) ? g_list[off + bBase + rr] : -1;
                stg[r] = (gi >= 0) ? *(const float4*)(emb + (size_t)gi * D + l * 4)
                                   : make_float4(0.f, 0.f, 0.f, 0.f);
            }
            if (tid < TN) {
                int gi = (tid < nB) ? g_list[off + bBase + tid] : -1;
                sgi = gi; slab = (gi >= 0) ? labels[gi] : -1;
                ssq = (gi >= 0) ? g_sq[gi] : 0.f;
            }
        };
        auto store = [&](int buf) {          // staged regs -> swizzled smem
            float* dB = sB + buf * TILE_WORDS;
#pragma unroll
            for (int r = 0; r < 8; r++) {
                int rr = w * 8 + r;
                int swz = (((rr >> 2) ^ (l & 15)) << 2) + (rr & 3);
#pragma unroll
                for (int c = 0; c < 4; c++)
                    dB[(4 * l + c) * PITCH + swz] = ((const float*)&stg[r])[c];
            }
            if (tid < TN) { bIdx[buf][tid] = sgi; bLab[buf][tid] = slab; bSq[buf][tid] = ssq; }
        };

        stage(0);
        for (int t = 0; t < nT; t++) {
            int buf = t & 1;
            store(buf);
            if (t + 1 < nT) stage(t + 1);    // LDG latency overlaps compute below
            __syncthreads();                 // tile t visible; also WAR fence

            const float* cB = sB + buf * TILE_WORDS;
            float acc[16] = {0.f,0.f,0.f,0.f, 0.f,0.f,0.f,0.f,
                             0.f,0.f,0.f,0.f, 0.f,0.f,0.f,0.f};
#pragma unroll 8
            for (int k = 0; k < D; k++) {
                int sw = ((k >> 2) & 15) << 2;
                float4 a = *(const float4*)&sA[k * PITCH + ((ty << 2) ^ sw)];
                float4 b = *(const float4*)&cB[k * PITCH + ((tx << 2) ^ sw)];
                acc[0]  += a.x * b.x; acc[1]  += a.x * b.y; acc[2]  += a.x * b.z; acc[3]  += a.x * b.w;
                acc[4]  += a.y * b.x; acc[5]  += a.y * b.y; acc[6]  += a.y * b.z; acc[7]  += a.y * b.w;
                acc[8]  += a.z * b.x; acc[9]  += a.z * b.y; acc[10] += a.z * b.z; acc[11] += a.z * b.w;
                acc[12] += a.w * b.x; acc[13] += a.w * b.y; acc[14] += a.w * b.z; acc[15] += a.w * b.w;
            }

            // selection key = bSq - 2*dot  (d2 minus per-anchor constant aSq)
#pragma unroll
            for (int j = 0; j < 4; j++) {
                int bj = bIdx[buf][tx * 4 + j];
                if (bj < 0) continue;
                int   bl  = bLab[buf][tx * 4 + j];
                float bsq = bSq[buf][tx * 4 + j];
#pragma unroll
                for (int i = 0; i < 4; i++) {
                    float kv = bsq - 2.0f * acc[i * 4 + j];
                    if (bl == al[i]) {
                        if (bj != ai[i] &&
                            (kv > pV[i] || (kv == pV[i] && bj < pI[i]))) { pV[i] = kv; pI[i] = bj; }
                    } else {
                        if (kv < nV[i] || (kv == nV[i] && bj < nI[i])) { nV[i] = kv; nI[i] = bj; }
                    }
                }
            }
        }

        // reduce across the 16 tx lanes (xor widths stay inside the half-warp)
#pragma unroll
        for (int i = 0; i < 4; i++) {
            float v = pV[i]; int ix = pI[i];
#pragma unroll
            for (int d = 8; d; d >>= 1) {
                float ov = __shfl_xor_sync(0xFFFFFFFFu, v, d);
                int   oi = __shfl_xor_sync(0xFFFFFFFFu, ix, d);
                if (oi >= 0 && (ix < 0 || ov > v || (ov == v && oi < ix))) { v = ov; ix = oi; }
            }
            float u = nV[i]; int jx = nI[i];
#pragma unroll
            for (int d = 8; d; d >>= 1) {
                float ou = __shfl_xor_sync(0xFFFFFFFFu, u, d);
                int   oj = __shfl_xor_sync(0xFFFFFFFFu, jx, d);
                if (oj >= 0 && (jx < 0 || ou < u || (ou == u && oj < jx))) { u = ou; jx = oj; }
            }
            if (tx == 0) { sPI[ty * 4 + i] = ix; sNI[ty * 4 + i] = jx; }
        }
        __syncthreads();

        // fused triplet epilogue: warp w handles anchors w*8 .. w*8+7
        for (int q = 0; q < 8; q++) {
            int la = w * 8 + q;
            int a = aIdx[la], p = sPI[la], n = sNI[la];
            if (a >= 0 && p >= 0 && n >= 0) {
                float4 av = *(const float4*)(emb + (size_t)a * D + l * 4);
                float4 pv = *(const float4*)(emb + (size_t)p * D + l * 4);
                float4 nv = *(const float4*)(emb + (size_t)n * D + l * 4);
                float sp = 0.f, sn = 0.f, d;
                d = av.x - pv.x + EPSV; sp += d * d;
                d = av.y - pv.y + EPSV; sp += d * d;
                d = av.z - pv.z + EPSV; sp += d * d;
                d = av.w - pv.w + EPSV; sp += d * d;
                d = av.x - nv.x + EPSV; sn += d * d;
                d = av.y - nv.y + EPSV; sn += d * d;
                d = av.z - nv.z + EPSV; sn += d * d;
                d = av.w - nv.w + EPSV; sn += d * d;
#pragma unroll
                for (int dd = 16; dd; dd >>= 1) {
                    sp += __shfl_xor_sync(0xFFFFFFFFu, sp, dd);
                    sn += __shfl_xor_sync(0xFFFFFFFFu, sn, dd);
                }
                if (l == 0) {
                    runSum += fmaxf(sqrtf(sp) - sqrtf(sn) + MARGIN, 0.0f);
                    runCnt += 1;
                }
            }
        }
    }

    // ---- per-block partial (fixed order -> deterministic) ----
    if (l == 0) { wSum[w] = runSum; wCnt[w] = runCnt; }
    __syncthreads();
    int bid = blockIdx.y * GX + blockIdx.x;
    if (tid == 0) {
        float s8 = 0.f; int c8 = 0;
#pragma unroll
        for (int i = 0; i < 8; i++) { s8 += wSum[i]; c8 += wCnt[i]; }
        g_psum[bid] = s8; g_pcnt[bid] = c8;
        __threadfence();
        unsigned done = atomicAdd(&g_ctr, 1u);
        lastBlk = (done == NBLK - 1);
    }
    __syncthreads();

    // ---- last block: deterministic tree reduction over 256 partials ----
    if (lastBlk) {
        __threadfence();
        __shared__ float rs[256];
        __shared__ int   rc[256];
        rs[tid] = g_psum[tid];
        rc[tid] = g_pcnt[tid];
        __syncthreads();
#pragma unroll
        for (int d = 128; d; d >>= 1) {
            if (tid < d) { rs[tid] += rs[tid + d]; rc[tid] += rc[tid + d]; }
            __syncthreads();
        }
        if (tid == 0) out[0] = (rc[0] > 0) ? (rs[0] / (float)rc[0]) : 0.0f;
    }
}

// ---------------------------------------------------------------------------
extern "C" void kernel_launch(void* const* d_in, const int* in_sizes, int n_in,
                              void* d_out, int out_size) {
    const float* emb    = (const float*)d_in[0];
    const int*   labels = (const int*)d_in[1];
    const int*   sbj    = (const int*)d_in[2];
    float*       out    = (float*)d_out;
    int B = in_sizes[1];
    if (B > MAXB) B = MAXB;

    cudaFuncSetAttribute(k_compute, cudaFuncAttributeMaxDynamicSharedMemorySize,
                         SMEM_BYTES);

    k_prep<<<257, 1024>>>(emb, sbj, B);
    k_compute<<<dim3(GX, NS), 256, SMEM_BYTES>>>(emb, labels, out);
}